// round 6
// baseline (speedup 1.0000x reference)
#include <cuda_runtime.h>
#include <math.h>

#define NPIX   262144
#define NCH    256
#define NK     24            // n_knots + degree + 1
#define ND     22            // second-difference rows
#define PPI    8             // pixels per block iteration
#define NTILES (NPIX / PPI)  // 32768
#define GRID   888           // 148 SMs * 6 blocks (occupancy target 5-6)

#define C1F 1.191042e-08f
#define C2F 1.4387769f

// ---------------- persistent device scratch (no allocations) ----------------
__device__ double   g_res;
__device__ double   g_ss;
__device__ double   g_bv;
__device__ unsigned g_count;

__global__ void __launch_bounds__(256, 5)
fused_kernel(const float* __restrict__ s_obs,
             const float* __restrict__ temperature,
             const float* __restrict__ beta,
             const float* __restrict__ view_factor,
             const float* __restrict__ s_sky,
             const float* __restrict__ s_ground,
             const float* __restrict__ phi,
             const float* __restrict__ wn,
             float* __restrict__ s_model,     // 4B aligned only (d_out+1)
             float* __restrict__ out_total,
             int write_total)
{
    __shared__ float wred[3][8];

    const int t    = threadIdx.x;       // t == channel
    const int wid  = t >> 5;
    const int lane = t & 31;

    // ---- per-channel constants (one-time; phi/wn tiny, L2-resident) ----
    const float* row = phi + t * NK;
    int k0 = 0;
    #pragma unroll
    for (int k = 0; k < NK; ++k) {
        if (row[k] != 0.0f) { k0 = k; break; }
    }
    if (k0 > NK - 4) k0 = NK - 4;
    const float w0 = row[k0],     w1 = row[k0 + 1];
    const float w2 = row[k0 + 2], w3 = row[k0 + 3];
    const float v   = wn[t];
    const float c1  = C1F * v * v * v;
    const float c2  = C2F * v;
    const float sg  = s_ground[t];
    const float dsg = s_sky[t] - sg;

    // smoothness assignment: threads 0..PPI*ND-1 (=176): (pixel sp, row sj)
    const int sp = t / ND, sj = t - sp * ND;
    const bool has_s = t < PPI * ND;

    float rs = 0.0f, bvs = 0.0f, sss = 0.0f;

    for (int tile = blockIdx.x; tile < NTILES; tile += GRID) {
        const int base = tile * PPI;

        // batch s_obs loads (streaming, 8 LDG in flight per warp)
        const unsigned ob = (unsigned)base * NCH + t;
        float so[PPI];
        #pragma unroll
        for (int p = 0; p < PPI; ++p)
            so[p] = __ldcs(&s_obs[ob + (unsigned)p * NCH]);

        // smoothness: direct L1-cached reads of beta (rows reused by whole block)
        if (has_s) {
            const float* bb = &beta[(unsigned)(base + sp) * NK];
            const float d = __ldg(&bb[sj]) - 2.0f * __ldg(&bb[sj + 1]) + __ldg(&bb[sj + 2]);
            sss = fmaf(d, d, sss);
        }

        // prefetch pixel 0 operands
        const float* bp = &beta[(unsigned)base * NK];
        float b0 = __ldg(&bp[k0]),     b1 = __ldg(&bp[k0 + 1]);
        float b2 = __ldg(&bp[k0 + 2]), b3 = __ldg(&bp[k0 + 3]);
        float Tc = __ldg(&temperature[base]);
        float Vc = __ldg(&view_factor[base]);

        #pragma unroll
        for (int p = 0; p < PPI; ++p) {
            // prefetch next pixel's operands before computing this one
            float nb0, nb1, nb2, nb3, nT, nV;
            if (p + 1 < PPI) {
                const float* np = &beta[(unsigned)(base + p + 1) * NK];
                nb0 = __ldg(&np[k0]);     nb1 = __ldg(&np[k0 + 1]);
                nb2 = __ldg(&np[k0 + 2]); nb3 = __ldg(&np[k0 + 3]);
                nT  = __ldg(&temperature[base + p + 1]);
                nV  = __ldg(&view_factor[base + p + 1]);
            }

            float e = w0 * b0;
            e = fmaf(w1, b1, e);
            e = fmaf(w2, b2, e);
            e = fmaf(w3, b3, e);

            const float arg = c2 * __frcp_rn(Tc);
            const float pl  = __fdividef(c1, __expf(arg) - 1.0f); // arg>=2.3
            const float xa  = fmaf(Vc, dsg, sg);
            const float sm  = fmaf(e, pl - xa, xa);

            __stcs(&s_model[ob + (unsigned)p * NCH], sm);

            const float r = so[p] - sm;
            rs  = fmaf(r, r, rs);
            bvs += fmaxf(fmaxf(0.01f - e, e - 0.99f), 0.0f);

            if (p + 1 < PPI) {
                b0 = nb0; b1 = nb1; b2 = nb2; b3 = nb3; Tc = nT; Vc = nV;
            }
        }
    }

    // ---- block reduction ----
    const unsigned m = 0xffffffffu;
    #pragma unroll
    for (int o = 16; o > 0; o >>= 1) {
        rs  += __shfl_down_sync(m, rs,  o);
        bvs += __shfl_down_sync(m, bvs, o);
        sss += __shfl_down_sync(m, sss, o);
    }
    if (lane == 0) { wred[0][wid] = rs; wred[1][wid] = bvs; wred[2][wid] = sss; }
    __syncthreads();

    if (t == 0) {
        double a = 0.0, b = 0.0, c = 0.0;
        #pragma unroll
        for (int i = 0; i < 8; ++i) {
            a += (double)wred[0][i];
            b += (double)wred[1][i];
            c += (double)wred[2][i];
        }
        atomicAdd(&g_res, a);
        atomicAdd(&g_bv,  b);
        atomicAdd(&g_ss,  c);
        __threadfence();
        const unsigned done = atomicAdd(&g_count, 1u);
        if (done == (unsigned)(GRID - 1)) {
            const double rr = atomicAdd(&g_res, 0.0);
            const double bb = atomicAdd(&g_bv,  0.0);
            const double cc = atomicAdd(&g_ss,  0.0);
            const double n  = (double)NPIX;
            if (write_total)
                out_total[0] = (float)(rr / n + 0.5 * cc / n + 10.0 * bb / n);
            g_res = 0.0; g_bv = 0.0; g_ss = 0.0; g_count = 0u;
        }
    }
}

// ---------------- launch ----------------
extern "C" void kernel_launch(void* const* d_in, const int* in_sizes, int n_in,
                              void* d_out, int out_size)
{
    const float* s_obs       = (const float*)d_in[0];
    const float* temperature = (const float*)d_in[1];
    const float* beta        = (const float*)d_in[2];
    const float* view_factor = (const float*)d_in[3];
    const float* s_sky       = (const float*)d_in[4];
    const float* s_ground    = (const float*)d_in[5];
    const float* phi         = (const float*)d_in[6];
    // d_in[7] = d_beta (2nd-difference operator, applied analytically)
    const float* wn          = (const float*)d_in[8];

    float* out = (float*)d_out;
    const int off = out_size - NPIX * NCH;   // expected 1 (total scalar first)
    float* smodel = out + (off > 0 ? off : 0);

    fused_kernel<<<GRID, 256>>>(s_obs, temperature, beta, view_factor,
                                s_sky, s_ground, phi, wn,
                                smodel, out, off > 0 ? 1 : 0);
}

// round 8
// speedup vs baseline: 1.3208x; 1.3208x over previous
#include <cuda_runtime.h>
#include <math.h>

#define NPIX   262144
#define NCH    256
#define NK     24            // n_knots + degree + 1
#define ND     22            // second-difference rows
#define PPI    8             // pixels per tile
#define NTILES (NPIX / PPI)  // 32768
#define GRID   740           // 148 SMs * 5 resident blocks

#define C1F 1.191042e-08f
#define C2F 1.4387769f

// ---------------- persistent device scratch (no allocations) ----------------
__device__ double   g_res;
__device__ double   g_ss;
__device__ double   g_bv;
__device__ unsigned g_count;

__global__ void __launch_bounds__(256, 5)
fused_kernel(const float* __restrict__ s_obs,
             const float* __restrict__ temperature,
             const float* __restrict__ beta,
             const float* __restrict__ view_factor,
             const float* __restrict__ s_sky,
             const float* __restrict__ s_ground,
             const float* __restrict__ phi,
             const float* __restrict__ wn,
             float* __restrict__ s_model,     // 4B aligned only (d_out+1)
             float* __restrict__ out_total,
             int write_total)
{
    __shared__ float  sb[2][PPI * NK];   // beta tiles, double buffered
    __shared__ float2 sTV[2][PPI];       // (1/T, vf) per pixel
    __shared__ float  wred[3][8];

    const int t    = threadIdx.x;        // t == channel
    const int wid  = t >> 5;
    const int lane = t & 31;

    // ---- per-channel constants (one-time; phi/wn tiny, L2-resident) ----
    const float* row = phi + t * NK;
    int k0 = 0;
    #pragma unroll
    for (int k = 0; k < NK; ++k) {
        if (row[k] != 0.0f) { k0 = k; break; }
    }
    if (k0 > NK - 4) k0 = NK - 4;
    const float w0 = row[k0],     w1 = row[k0 + 1];
    const float w2 = row[k0 + 2], w3 = row[k0 + 3];
    const float v   = wn[t];
    const float c1  = C1F * v * v * v;
    const float c2  = C2F * v;
    const float sg  = s_ground[t];
    const float dsg = s_sky[t] - sg;

    // smoothness assignment: threads 0..PPI*ND-1 (=176): (pixel sp, row sj)
    const int  ssoff = (t / ND) * NK + (t - (t / ND) * ND);
    const bool has_s = t < PPI * ND;

    float rs = 0.0f, bvs = 0.0f, sss = 0.0f;

    // stage beta (192 floats) + (1/T, vf) for a tile into buffer `buf`
    auto stage = [&](int buf, int tile) {
        const int base = tile * PPI;
        if (t < PPI * NK) {
            sb[buf][t] = __ldcs(&beta[(unsigned)base * NK + t]);
        } else if (t < PPI * NK + PPI) {
            sTV[buf][t - PPI * NK].x = __frcp_rn(temperature[base + (t - PPI * NK)]);
        } else if (t < PPI * NK + 2 * PPI) {
            sTV[buf][t - (PPI * NK + PPI)].y = view_factor[base + (t - (PPI * NK + PPI))];
        }
    };

    int tile = blockIdx.x;
    stage(0, tile);
    __syncthreads();

    int buf = 0;
    for (; tile < NTILES; tile += GRID) {
        const int nxt = tile + GRID;
        if (nxt < NTILES) stage(buf ^ 1, nxt);

        // batch s_obs loads (8 LDG.32 in flight per warp)
        const unsigned ob = (unsigned)tile * (PPI * NCH) + (unsigned)t;
        float so[PPI];
        #pragma unroll
        for (int p = 0; p < PPI; ++p)
            so[p] = __ldcs(&s_obs[ob + (unsigned)(p * NCH)]);

        // smoothness from the staged beta tile
        if (has_s) {
            const float* bb = &sb[buf][ssoff];
            const float d = bb[0] - 2.0f * bb[1] + bb[2];
            sss = fmaf(d, d, sss);
        }

        #pragma unroll
        for (int p = 0; p < PPI; ++p) {
            const float* b = &sb[buf][p * NK + k0];
            float e = w0 * b[0];
            e = fmaf(w1, b[1], e);
            e = fmaf(w2, b[2], e);
            e = fmaf(w3, b[3], e);

            const float2 tv  = sTV[buf][p];
            const float  arg = c2 * tv.x;
            const float  pl  = __fdividef(c1, __expf(arg) - 1.0f); // arg>=2.3
            const float  xa  = fmaf(tv.y, dsg, sg);
            const float  sm  = fmaf(e, pl - xa, xa);

            __stcs(&s_model[ob + (unsigned)(p * NCH)], sm);

            const float r = so[p] - sm;
            rs  = fmaf(r, r, rs);
            // relu(.01-e)+relu(e-.99) == max(|e-0.5|-0.49, 0)  (mutually exclusive)
            bvs += fmaxf(fabsf(e - 0.5f) - 0.49f, 0.0f);
        }

        __syncthreads();
        buf ^= 1;
    }

    // ---- block reduction ----
    const unsigned m = 0xffffffffu;
    #pragma unroll
    for (int o = 16; o > 0; o >>= 1) {
        rs  += __shfl_down_sync(m, rs,  o);
        bvs += __shfl_down_sync(m, bvs, o);
        sss += __shfl_down_sync(m, sss, o);
    }
    if (lane == 0) { wred[0][wid] = rs; wred[1][wid] = bvs; wred[2][wid] = sss; }
    __syncthreads();

    if (t == 0) {
        double a = 0.0, b = 0.0, c = 0.0;
        #pragma unroll
        for (int i = 0; i < 8; ++i) {
            a += (double)wred[0][i];
            b += (double)wred[1][i];
            c += (double)wred[2][i];
        }
        atomicAdd(&g_res, a);
        atomicAdd(&g_bv,  b);
        atomicAdd(&g_ss,  c);
        __threadfence();
        const unsigned done = atomicAdd(&g_count, 1u);
        if (done == (unsigned)(GRID - 1)) {
            const double rr = atomicAdd(&g_res, 0.0);
            const double bb = atomicAdd(&g_bv,  0.0);
            const double cc = atomicAdd(&g_ss,  0.0);
            const double n  = (double)NPIX;
            if (write_total)
                out_total[0] = (float)(rr / n + 0.5 * cc / n + 10.0 * bb / n);
            g_res = 0.0; g_bv = 0.0; g_ss = 0.0; g_count = 0u;
        }
    }
}

// ---------------- launch ----------------
extern "C" void kernel_launch(void* const* d_in, const int* in_sizes, int n_in,
                              void* d_out, int out_size)
{
    const float* s_obs       = (const float*)d_in[0];
    const float* temperature = (const float*)d_in[1];
    const float* beta        = (const float*)d_in[2];
    const float* view_factor = (const float*)d_in[3];
    const float* s_sky       = (const float*)d_in[4];
    const float* s_ground    = (const float*)d_in[5];
    const float* phi         = (const float*)d_in[6];
    // d_in[7] = d_beta (2nd-difference operator, applied analytically)
    const float* wn          = (const float*)d_in[8];

    float* out = (float*)d_out;
    const int off = out_size - NPIX * NCH;   // expected 1 (total scalar first)
    float* smodel = out + (off > 0 ? off : 0);

    fused_kernel<<<GRID, 256>>>(s_obs, temperature, beta, view_factor,
                                s_sky, s_ground, phi, wn,
                                smodel, out, off > 0 ? 1 : 0);
}

// round 10
// speedup vs baseline: 1.4417x; 1.0915x over previous
#include <cuda_runtime.h>
#include <math.h>

#define NPIX   262144
#define NCH    256
#define NK     24            // n_knots + degree + 1
#define ND     22            // second-difference rows
#define PPI    8             // pixels per tile
#define PF     4             // s_obs prefetch ring depth
#define NTILES (NPIX / PPI)  // 32768
#define GRID   740           // 148 SMs * 5 resident blocks

#define C1F 1.191042e-08f
#define C2F 1.4387769f

// ---------------- persistent device scratch (no allocations) ----------------
__device__ double   g_res;
__device__ double   g_ss;
__device__ double   g_bv;
__device__ unsigned g_count;

__global__ void __launch_bounds__(256, 5)
fused_kernel(const float* __restrict__ s_obs,
             const float* __restrict__ temperature,
             const float* __restrict__ beta,
             const float* __restrict__ view_factor,
             const float* __restrict__ s_sky,
             const float* __restrict__ s_ground,
             const float* __restrict__ phi,
             const float* __restrict__ wn,
             float* __restrict__ s_model,     // 4B aligned only (d_out+1)
             float* __restrict__ out_total,
             int write_total)
{
    __shared__ float  sb[2][PPI * NK];   // beta tiles, double buffered
    __shared__ float2 sTV[2][PPI];       // (1/T, vf) per pixel
    __shared__ float  wred[3][8];

    const int t    = threadIdx.x;        // t == channel
    const int wid  = t >> 5;
    const int lane = t & 31;

    // ---- per-channel constants (one-time; phi/wn tiny, L2-resident) ----
    const float* row = phi + t * NK;
    int k0 = 0;
    #pragma unroll
    for (int k = 0; k < NK; ++k) {
        if (row[k] != 0.0f) { k0 = k; break; }
    }
    if (k0 > NK - 4) k0 = NK - 4;
    const float w0 = row[k0],     w1 = row[k0 + 1];
    const float w2 = row[k0 + 2], w3 = row[k0 + 3];
    const float v   = wn[t];
    const float c1  = C1F * v * v * v;
    const float c2  = C2F * v;
    const float sg  = s_ground[t];
    const float dsg = s_sky[t] - sg;

    // smoothness assignment: threads 0..PPI*ND-1 (=176): (pixel sp, row sj)
    const int  ssoff = (t / ND) * NK + (t - (t / ND) * ND);
    const bool has_s = t < PPI * ND;

    float rs = 0.0f, bvs = 0.0f, sss = 0.0f;

    // stage beta (192 floats) + (1/T, vf) for a tile into buffer `buf`
    auto stage = [&](int buf, int tile) {
        const int base = tile * PPI;
        if (t < PPI * NK) {
            sb[buf][t] = __ldcs(&beta[(unsigned)base * NK + t]);
        } else if (t < PPI * NK + PPI) {
            sTV[buf][t - PPI * NK].x = __frcp_rn(temperature[base + (t - PPI * NK)]);
        } else if (t < PPI * NK + 2 * PPI) {
            sTV[buf][t - (PPI * NK + PPI)].y = view_factor[base + (t - (PPI * NK + PPI))];
        }
    };

    int tile = blockIdx.x;
    stage(0, tile);
    __syncthreads();

    int buf = 0;
    for (; tile < NTILES; tile += GRID) {
        const int nxt = tile + GRID;
        if (nxt < NTILES) stage(buf ^ 1, nxt);

        const unsigned ob = (unsigned)tile * (PPI * NCH) + (unsigned)t;

        // rolling s_obs prefetch ring (depth PF): steady, non-bursty LDG stream
        float so[PF];
        #pragma unroll
        for (int p = 0; p < PF; ++p)
            so[p] = __ldcs(&s_obs[ob + (unsigned)(p * NCH)]);

        // smoothness from the staged beta tile
        if (has_s) {
            const float* bb = &sb[buf][ssoff];
            const float d = bb[0] - 2.0f * bb[1] + bb[2];
            sss = fmaf(d, d, sss);
        }

        #pragma unroll
        for (int p = 0; p < PPI; ++p) {
            // issue next prefetch early in the iteration (one LDG per ~25 inst)
            if (p + PF < PPI)
                so[(p + PF) & (PF - 1)] =
                    __ldcs(&s_obs[ob + (unsigned)((p + PF) * NCH)]);

            const float* b = &sb[buf][p * NK + k0];
            float e = w0 * b[0];
            e = fmaf(w1, b[1], e);
            e = fmaf(w2, b[2], e);
            e = fmaf(w3, b[3], e);

            const float2 tv  = sTV[buf][p];
            const float  arg = c2 * tv.x;
            const float  pl  = __fdividef(c1, __expf(arg) - 1.0f); // arg>=2.3
            const float  xa  = fmaf(tv.y, dsg, sg);
            const float  sm  = fmaf(e, pl - xa, xa);

            __stcs(&s_model[ob + (unsigned)(p * NCH)], sm);

            const float r = so[p & (PF - 1)] - sm;
            rs  = fmaf(r, r, rs);
            // relu(.01-e)+relu(e-.99) == max(|e-0.5|-0.49, 0)
            bvs += fmaxf(fabsf(e - 0.5f) - 0.49f, 0.0f);
        }

        __syncthreads();
        buf ^= 1;
    }

    // ---- block reduction ----
    const unsigned m = 0xffffffffu;
    #pragma unroll
    for (int o = 16; o > 0; o >>= 1) {
        rs  += __shfl_down_sync(m, rs,  o);
        bvs += __shfl_down_sync(m, bvs, o);
        sss += __shfl_down_sync(m, sss, o);
    }
    if (lane == 0) { wred[0][wid] = rs; wred[1][wid] = bvs; wred[2][wid] = sss; }
    __syncthreads();

    if (t == 0) {
        double a = 0.0, b = 0.0, c = 0.0;
        #pragma unroll
        for (int i = 0; i < 8; ++i) {
            a += (double)wred[0][i];
            b += (double)wred[1][i];
            c += (double)wred[2][i];
        }
        atomicAdd(&g_res, a);
        atomicAdd(&g_bv,  b);
        atomicAdd(&g_ss,  c);
        __threadfence();
        const unsigned done = atomicAdd(&g_count, 1u);
        if (done == (unsigned)(GRID - 1)) {
            const double rr = atomicAdd(&g_res, 0.0);
            const double bb = atomicAdd(&g_bv,  0.0);
            const double cc = atomicAdd(&g_ss,  0.0);
            const double n  = (double)NPIX;
            if (write_total)
                out_total[0] = (float)(rr / n + 0.5 * cc / n + 10.0 * bb / n);
            g_res = 0.0; g_bv = 0.0; g_ss = 0.0; g_count = 0u;
        }
    }
}

// ---------------- launch ----------------
extern "C" void kernel_launch(void* const* d_in, const int* in_sizes, int n_in,
                              void* d_out, int out_size)
{
    const float* s_obs       = (const float*)d_in[0];
    const float* temperature = (const float*)d_in[1];
    const float* beta        = (const float*)d_in[2];
    const float* view_factor = (const float*)d_in[3];
    const float* s_sky       = (const float*)d_in[4];
    const float* s_ground    = (const float*)d_in[5];
    const float* phi         = (const float*)d_in[6];
    // d_in[7] = d_beta (2nd-difference operator, applied analytically)
    const float* wn          = (const float*)d_in[8];

    float* out = (float*)d_out;
    const int off = out_size - NPIX * NCH;   // expected 1 (total scalar first)
    float* smodel = out + (off > 0 ? off : 0);

    fused_kernel<<<GRID, 256>>>(s_obs, temperature, beta, view_factor,
                                s_sky, s_ground, phi, wn,
                                smodel, out, off > 0 ? 1 : 0);
}